// round 1
// baseline (speedup 1.0000x reference)
#include <cuda_runtime.h>
#include <cuda_bf16.h>

// ListMLE loss with tail term.
// Inputs (metadata order): output f32 [B,V], target i32 [B], tails i32 [B,T], tail_len i32 [B]
// Output: f32 [B]
//
// One CTA per row. HBM-bound streaming exp-sum over V, then O(T) serial tail math.

#define THREADS 256

__global__ __launch_bounds__(THREADS)
void listmle_tail_kernel(const float* __restrict__ output,
                         const int*   __restrict__ target,
                         const int*   __restrict__ tails,
                         const int*   __restrict__ tail_len,
                         float*       __restrict__ out,
                         int V, int T)
{
    const int b = blockIdx.x;
    const float* __restrict__ row = output + (size_t)b * (size_t)V;

    // ---- streaming exp-sum over the row (float4 vectorized) ----
    float acc = 0.0f;
    const int nvec = V >> 2;                    // V=50000 -> 12500 float4
    const float4* __restrict__ row4 = reinterpret_cast<const float4*>(row);
    for (int i = threadIdx.x; i < nvec; i += THREADS) {
        float4 v = __ldg(row4 + i);
        acc += __expf(v.x) + __expf(v.y) + __expf(v.z) + __expf(v.w);
    }
    // scalar remainder (none for V=50000, kept for generality)
    for (int i = (nvec << 2) + threadIdx.x; i < V; i += THREADS) {
        acc += __expf(__ldg(row + i));
    }

    // ---- block reduction ----
    __shared__ float warpsum[THREADS / 32];
    const int lane = threadIdx.x & 31;
    const int wid  = threadIdx.x >> 5;
    #pragma unroll
    for (int o = 16; o > 0; o >>= 1)
        acc += __shfl_xor_sync(0xFFFFFFFFu, acc, o);
    if (lane == 0) warpsum[wid] = acc;

    // ---- parallel tail gather (threads 0..T-1) ----
    extern __shared__ float dyn_sh[];
    float* s_sh  = dyn_sh;        // [T]
    float* es_sh = dyn_sh + T;    // [T]
    const int L = min(tail_len[b], T);
    if (threadIdx.x < T) {
        const int t = threadIdx.x;
        float sv = 0.0f, ev = 0.0f;
        if (t < L) {
            const int idx = tails[b * T + t];
            sv = __ldg(row + idx);
            ev = __expf(sv);
        }
        s_sh[t]  = sv;
        es_sh[t] = ev;
    }
    __syncthreads();

    // ---- final serial tail math on thread 0 ----
    if (threadIdx.x == 0) {
        float total = 0.0f;
        #pragma unroll
        for (int w = 0; w < THREADS / 32; ++w) total += warpsum[w];

        const float tgt = __ldg(row + target[b]);

        float sum_es = 0.0f, above = 0.0f;
        for (int t = 0; t < L; ++t) {
            sum_es += es_sh[t];
            above  += s_sh[t];
        }
        const float others = total - __expf(tgt) - sum_es;

        // below_sum = sum_{k=0..L-1} log( suffix_sum(es, k) + others )
        float c = 0.0f, below = 0.0f;
        for (int k = L - 1; k >= 0; --k) {
            c += es_sh[k];
            below += __logf(c + others);
        }

        const float log_pl    = tgt - __logf(total);
        const float tail_term = (L > 0) ? (above - below) : 0.0f;
        out[b] = -(log_pl + tail_term);
    }
}

extern "C" void kernel_launch(void* const* d_in, const int* in_sizes, int n_in,
                              void* d_out, int out_size)
{
    const float* output   = (const float*)d_in[0];
    const int*   target   = (const int*)  d_in[1];
    const int*   tails    = (const int*)  d_in[2];
    const int*   tail_len = (const int*)  d_in[3];
    float*       out      = (float*)      d_out;

    const int B = in_sizes[1];             // 1024
    const int V = in_sizes[0] / B;         // 50000
    const int T = in_sizes[2] / B;         // 50

    const size_t shmem = 2 * (size_t)T * sizeof(float);
    listmle_tail_kernel<<<B, THREADS, shmem>>>(output, target, tails, tail_len, out, V, T);
}

// round 2
// speedup vs baseline: 1.0009x; 1.0009x over previous
#include <cuda_runtime.h>
#include <cuda_bf16.h>

// ListMLE loss with tail term. One CTA per row (B=1024), HBM-bound streaming
// exp-sum over V=50000, tail math parallelized across threads.
//
// Occupancy contract: 148 SMs * 7 CTAs/SM = 1036 >= 1024 CTAs -> single wave.
// __launch_bounds__(256, 7) keeps regs <= 36 so occupancy stays at 7.

#define THREADS 256

__global__ __launch_bounds__(THREADS, 7)
void listmle_tail_kernel(const float* __restrict__ output,
                         const int*   __restrict__ target,
                         const int*   __restrict__ tails,
                         const int*   __restrict__ tail_len,
                         float*       __restrict__ out,
                         int V, int T)
{
    const int b = blockIdx.x;
    const float* __restrict__ row = output + (size_t)b * (size_t)V;

    extern __shared__ float dyn_sh[];
    float* es_sh = dyn_sh;           // [T] exp(s), then overwritten with suffix sums
    float* s_sh  = dyn_sh + T;       // [T] raw tail scores
    float* lg_sh = dyn_sh + 2 * T;   // [T] per-position logs
    __shared__ float warpsum[THREADS / 32];
    __shared__ float sh_total, sh_others;

    const int L = min(__ldg(tail_len + b), T);

    // ---- early tail gather: random-access loads issued BEFORE the streaming
    //      loop so their DRAM latency hides under the bulk reads ----
    float tgt = 0.0f;
    if (threadIdx.x == 0) {
        tgt = __ldg(row + __ldg(target + b));
    }
    if (threadIdx.x < T) {
        const int t = threadIdx.x;
        float sv = 0.0f, ev = 0.0f;
        if (t < L) {
            sv = __ldg(row + __ldg(tails + b * T + t));
            ev = __expf(sv);
        }
        s_sh[t]  = sv;
        es_sh[t] = ev;
    }

    // ---- streaming exp-sum: 2x float4 unroll, independent accumulators,
    //      evict-first loads (read-once data, don't pollute L2) ----
    const int nvec = V >> 2;
    const float4* __restrict__ row4 = reinterpret_cast<const float4*>(row);
    float a0 = 0.0f, a1 = 0.0f;
    int i = threadIdx.x;
    for (; i + THREADS < nvec; i += 2 * THREADS) {
        float4 v0 = __ldcs(row4 + i);
        float4 v1 = __ldcs(row4 + i + THREADS);
        a0 += (__expf(v0.x) + __expf(v0.y)) + (__expf(v0.z) + __expf(v0.w));
        a1 += (__expf(v1.x) + __expf(v1.y)) + (__expf(v1.z) + __expf(v1.w));
    }
    for (; i < nvec; i += THREADS) {
        float4 v = __ldcs(row4 + i);
        a0 += (__expf(v.x) + __expf(v.y)) + (__expf(v.z) + __expf(v.w));
    }
    for (int j = (nvec << 2) + threadIdx.x; j < V; j += THREADS) {
        a0 += __expf(__ldcs(row + j));
    }

    // ---- block reduction ----
    float acc = a0 + a1;
    const int lane = threadIdx.x & 31;
    const int wid  = threadIdx.x >> 5;
    #pragma unroll
    for (int o = 16; o > 0; o >>= 1)
        acc += __shfl_xor_sync(0xFFFFFFFFu, acc, o);
    if (lane == 0) warpsum[wid] = acc;
    __syncthreads();

    // ---- thread 0: total, suffix-sum scan (FADD only, cheap), others ----
    float above = 0.0f;   // persists in thread 0's registers across syncs
    if (threadIdx.x == 0) {
        float total = 0.0f;
        #pragma unroll
        for (int w = 0; w < THREADS / 32; ++w) total += warpsum[w];

        float c = 0.0f;
        for (int k = L - 1; k >= 0; --k) {
            c += es_sh[k];        // suffix sum of exp(s)
            es_sh[k] = c;
            above += s_sh[k];
        }
        sh_total  = total;
        sh_others = total - __expf(tgt) - c;   // c == sum_es
    }
    __syncthreads();

    // ---- parallel logs: each tail position independent ----
    if (threadIdx.x < L) {
        lg_sh[threadIdx.x] = __logf(es_sh[threadIdx.x] + sh_others);
    }
    __syncthreads();

    // ---- thread 0: final combine ----
    if (threadIdx.x == 0) {
        float below = 0.0f;
        for (int k = 0; k < L; ++k) below += lg_sh[k];
        const float log_pl    = tgt - __logf(sh_total);
        const float tail_term = (L > 0) ? (above - below) : 0.0f;
        out[b] = -(log_pl + tail_term);
    }
}

extern "C" void kernel_launch(void* const* d_in, const int* in_sizes, int n_in,
                              void* d_out, int out_size)
{
    const float* output   = (const float*)d_in[0];
    const int*   target   = (const int*)  d_in[1];
    const int*   tails    = (const int*)  d_in[2];
    const int*   tail_len = (const int*)  d_in[3];
    float*       out      = (float*)      d_out;

    const int B = in_sizes[1];             // 1024
    const int V = in_sizes[0] / B;         // 50000
    const int T = in_sizes[2] / B;         // 50

    const size_t shmem = 3 * (size_t)T * sizeof(float);
    listmle_tail_kernel<<<B, THREADS, shmem>>>(output, target, tails, tail_len, out, V, T);
}